// round 14
// baseline (speedup 1.0000x reference)
#include <cuda_runtime.h>
#include <cuda_fp16.h>

#define M_DIM 2048
#define N_DIM 8192
#define N_ITERS 1000
#define TAU 1e-4f
#define SIGMA 1e-4f
#define NBLK 148
#define NTHR 1024

#define PROWS 13            // panel rows resident in SMEM (+1 register row)
#define PPAD 160            // padded partial rows (148 real, 12 always-zero)

// ---------------- device globals (allocation-free scratch) ----------------
__device__ float g_dxbar[N_DIM];          // delta-xbar published by owners
__device__ float g_lam[M_DIM];
__device__ float g_part[PPAD * N_DIM];    // fp32 partials; rows 148+ stay 0
__device__ unsigned g_flags[NBLK * 32];   // 1 flag / 128B line

// ---------------- smem layout (bytes) ----------------
#define OFF_PANEL 0                        // 13 rows x 8192 half = 212992
#define OFF_RED   212992                   // 16x64 fp32 = 4096
#define OFF_Y     (OFF_RED + 4096)         // 16 fp32  -> 217152
#define OFF_DY    (OFF_Y + 64)             // 16 fp32
#define OFF_D     (OFF_DY + 64)            // 16 fp32
#define OFF_X     (OFF_D + 64)             // 64 fp32
#define OFF_XBP   (OFF_X + 256)            // 64 fp32 (prev xbar)
#define OFF_C     (OFF_XBP + 256)          // 64 fp32
#define OFF_B     (OFF_C + 256)            // 16 fp32
#define SMEM_BYTES (OFF_B + 64)
#define OFF_LAM   0                        // finale reuse of panel: 2048 fp32

// ---------------------------------------------------------------------------
__global__ void init_kernel() {
    int i = blockIdx.x * blockDim.x + threadIdx.x;
    if (i < N_DIM) g_dxbar[i] = 0.f;
    if (i < NBLK * 32) g_flags[i] = 0u;
}

// ---- GPU-scope sync primitives (R13-proven) --------------------------------
__device__ __forceinline__ unsigned ld_relaxed(const unsigned* p) {
    unsigned v;
    asm volatile("ld.relaxed.gpu.global.u32 %0, [%1];" : "=r"(v) : "l"(p) : "memory");
    return v;
}
__device__ __forceinline__ void st_release(unsigned* p, unsigned v) {
    asm volatile("st.release.gpu.global.u32 [%0], %1;" :: "l"(p), "r"(v) : "memory");
}
__device__ __forceinline__ void fence_acq() {
    asm volatile("fence.acq_rel.gpu;" ::: "memory");
}
__device__ __forceinline__ void grid_barrier(unsigned target) {
    __syncthreads();
    if (threadIdx.x == 0)
        st_release(&g_flags[blockIdx.x * 32], target);
    if (threadIdx.x < NBLK) {
        while (ld_relaxed(&g_flags[threadIdx.x * 32]) < target) { }
        fence_acq();
    }
    __syncthreads();
}

// convert 8 fp16 (uint4) -> 8 fp32
__device__ __forceinline__ void cvt8(uint4 a, float* f) {
    float2 t;
    t = __half22float2(*reinterpret_cast<__half2*>(&a.x)); f[0] = t.x; f[1] = t.y;
    t = __half22float2(*reinterpret_cast<__half2*>(&a.y)); f[2] = t.x; f[3] = t.y;
    t = __half22float2(*reinterpret_cast<__half2*>(&a.z)); f[4] = t.x; f[5] = t.y;
    t = __half22float2(*reinterpret_cast<__half2*>(&a.w)); f[6] = t.x; f[7] = t.y;
}

// pack 8 fp32 -> uint4 of fp16
__device__ __forceinline__ uint4 pack8(float4 v0, float4 v1) {
    uint4 h;
    *reinterpret_cast<__half2*>(&h.x) = __floats2half2_rn(v0.x, v0.y);
    *reinterpret_cast<__half2*>(&h.y) = __floats2half2_rn(v0.z, v0.w);
    *reinterpret_cast<__half2*>(&h.z) = __floats2half2_rn(v1.x, v1.y);
    *reinterpret_cast<__half2*>(&h.w) = __floats2half2_rn(v1.z, v1.w);
    return h;
}

// ---------------------------------------------------------------------------
__global__ void __launch_bounds__(NTHR, 1)
pdhg_kernel(const float* __restrict__ A, const float* __restrict__ b,
            const float* __restrict__ c, float* __restrict__ out) {
    extern __shared__ char sm[];
    const int tid  = threadIdx.x;
    const int warp = tid >> 5;
    const int lane = tid & 31;
    const int blk  = blockIdx.x;

    const int r0 = (blk * M_DIM) / NBLK;
    const int nr = ((blk + 1) * M_DIM) / NBLK - r0;   // 13 or 14
    const int c0 = (blk * N_DIM) / NBLK;
    const int nc = ((blk + 1) * N_DIM) / NBLK - c0;   // 55 or 56

    float* s_red  = (float*)(sm + OFF_RED);
    float* y_sm   = (float*)(sm + OFF_Y);
    float* dy_sm  = (float*)(sm + OFF_DY);
    float* D_sm   = (float*)(sm + OFF_D);
    float* x_sm   = (float*)(sm + OFF_X);
    float* xbp_sm = (float*)(sm + OFF_XBP);
    float* c_sm   = (float*)(sm + OFF_C);
    float* b_sm   = (float*)(sm + OFF_B);
    const uint4* P4 = (const uint4*)(sm + OFF_PANEL);

    // ---- prologue: convert 13 fp32 rows -> fp16 SMEM panel; 14th -> regs ----
    {
        const float4* A4 = (const float4*)A;
        uint4* W4 = (uint4*)(sm + OFF_PANEL);
        for (int r = 0; r < PROWS; r++) {
            float4 v0 = A4[((size_t)(r0 + r)) * 2048 + 2 * tid];
            float4 v1 = A4[((size_t)(r0 + r)) * 2048 + 2 * tid + 1];
            W4[r * 1024 + tid] = pack8(v0, v1);
        }
        if (tid < 16) { y_sm[tid] = 0.f; dy_sm[tid] = 0.f; D_sm[tid] = 0.f; }
        if (tid < nr) b_sm[tid] = b[r0 + tid];
        if (tid < nc) { x_sm[tid] = 0.f; xbp_sm[tid] = 0.f; c_sm[tid] = c[c0 + tid]; }
    }
    uint4 a_stream;
    {
        const float4* A4 = (const float4*)A;
        float4 v0 = A4[((size_t)(r0 + PROWS)) * 2048 + 2 * tid];
        float4 v1 = A4[((size_t)(r0 + PROWS)) * 2048 + 2 * tid + 1];
        a_stream = pack8(v0, v1);
    }
    __syncthreads();

    unsigned epoch = 0;
    // persistent partial accumulators o_k = (A^T y)_k for this thread's 8 cols
    float o0 = 0.f, o1 = 0.f, o2 = 0.f, o3 = 0.f;
    float o4 = 0.f, o5 = 0.f, o6 = 0.f, o7 = 0.f;

    for (int it = 0; it < N_ITERS; it++) {
        // ====== Phase Y (incremental): D_i += A_i · dxbar ==================
        float v[16];
        {
            const float4* gdx4 = (const float4*)g_dxbar;
            float4 dxa = __ldcg(gdx4 + 2 * tid);
            float4 dxb = __ldcg(gdx4 + 2 * tid + 1);
            unsigned nz = __float_as_uint(dxa.x) | __float_as_uint(dxa.y) |
                          __float_as_uint(dxa.z) | __float_as_uint(dxa.w) |
                          __float_as_uint(dxb.x) | __float_as_uint(dxb.y) |
                          __float_as_uint(dxb.z) | __float_as_uint(dxb.w);
            if (nz) {
                #pragma unroll
                for (int i = 0; i < 14; i++) {
                    uint4 a = (i < PROWS) ? P4[i * 1024 + tid] : a_stream;
                    float f[8];
                    cvt8(a, f);
                    v[i] = f[0]*dxa.x + f[1]*dxa.y + f[2]*dxa.z + f[3]*dxa.w +
                           f[4]*dxb.x + f[5]*dxb.y + f[6]*dxb.z + f[7]*dxb.w;
                }
            } else {
                #pragma unroll
                for (int i = 0; i < 14; i++) v[i] = 0.f;
            }
            v[14] = 0.f; v[15] = 0.f;
        }
        // butterfly multi-row warp reduction (proven)
        {
            #pragma unroll
            for (int k = 0; k < 8; k++) {
                float s = (lane & 16) ? v[k] : v[k + 8];
                float r = __shfl_xor_sync(0xffffffffu, s, 16);
                v[k] = ((lane & 16) ? v[k + 8] : v[k]) + r;
            }
            #pragma unroll
            for (int k = 0; k < 4; k++) {
                float s = (lane & 8) ? v[k] : v[k + 4];
                float r = __shfl_xor_sync(0xffffffffu, s, 8);
                v[k] = ((lane & 8) ? v[k + 4] : v[k]) + r;
            }
            #pragma unroll
            for (int k = 0; k < 2; k++) {
                float s = (lane & 4) ? v[k] : v[k + 2];
                float r = __shfl_xor_sync(0xffffffffu, s, 4);
                v[k] = ((lane & 4) ? v[k + 2] : v[k]) + r;
            }
            {
                float s = (lane & 2) ? v[0] : v[1];
                float r = __shfl_xor_sync(0xffffffffu, s, 2);
                v[0] = ((lane & 2) ? v[1] : v[0]) + r;
            }
            v[0] += __shfl_xor_sync(0xffffffffu, v[0], 1);
            int row = (((lane >> 4) & 1) << 3) | (((lane >> 3) & 1) << 2) |
                      (((lane >> 2) & 1) << 1) | ((lane >> 1) & 1);
            if ((lane & 1) == 0) s_red[row * 32 + warp] = v[0];
        }
        __syncthreads();
        if (warp < 16) {
            float t = s_red[warp * 32 + lane];
            #pragma unroll
            for (int o = 16; o > 0; o >>= 1)
                t += __shfl_down_sync(0xffffffffu, t, o);
            if (lane == 0 && warp < nr) {
                float Dn = D_sm[warp] + t;
                D_sm[warp] = Dn;
                float yo = y_sm[warp];
                float yn = fminf(0.f, yo + SIGMA * Dn - SIGMA * b_sm[warp]);
                dy_sm[warp] = yn - yo;
                y_sm[warp] = yn;
            }
        }
        __syncthreads();

        // ====== Phase X (incremental): o_k += a_ik * dy_i, skip dy==0 ======
        {
            #pragma unroll
            for (int i = 0; i < 14; i++) {
                float dy = dy_sm[i];                   // block-uniform
                if (dy != 0.f) {
                    uint4 a = (i < PROWS) ? P4[i * 1024 + tid] : a_stream;
                    float f[8];
                    cvt8(a, f);
                    o0 += f[0] * dy; o1 += f[1] * dy;
                    o2 += f[2] * dy; o3 += f[3] * dy;
                    o4 += f[4] * dy; o5 += f[5] * dy;
                    o6 += f[6] * dy; o7 += f[7] * dy;
                }
            }
            float4* O4 = (float4*)(g_part + (size_t)blk * N_DIM + tid * 8);
            __stcg(O4,     make_float4(o0, o1, o2, o3));
            __stcg(O4 + 1, make_float4(o4, o5, o6, o7));
        }
        grid_barrier(++epoch);

        // ===== owner reduce (uniform 10 loads; padded rows are static 0) ===
        {
            int g  = tid >> 6;
            int jc = tid & 63;
            if (jc < nc) {
                float r = 0.f;
                #pragma unroll
                for (int k = 0; k < 10; k++)
                    r += __ldcg(g_part + (size_t)(g + k * 16) * N_DIM + c0 + jc);
                s_red[g * 64 + jc] = r;
            }
            __syncthreads();
            if (tid < nc) {
                float dot = 0.f;
                #pragma unroll
                for (int gg = 0; gg < 16; gg++) dot += s_red[gg * 64 + tid];
                float xo = x_sm[tid];
                float xn = fmaxf(0.f, xo - TAU * dot - TAU * c_sm[tid]);
                x_sm[tid] = xn;
                float xbn = 2.f * xn - xo;
                __stcg(&g_dxbar[c0 + tid], xbn - xbp_sm[tid]);
                xbp_sm[tid] = xbn;
            }
        }
        grid_barrier(++epoch);
    }

    // ---- Finalize: out = [x, lam, nu] ----
    if (tid < nc) out[c0 + tid] = x_sm[tid];
    if (tid < nr) {
        float l = fmaxf(0.f, -y_sm[tid]);
        __stcg(&g_lam[r0 + tid], l);
        out[N_DIM + r0 + tid] = l;
    }
    grid_barrier(++epoch);

    // nu = relu(c - A^T @ lam), against ORIGINAL fp32 A (one pass, accuracy)
    {
        float* s_lam = (float*)(sm + OFF_LAM);
        #pragma unroll
        for (int t = 0; t < 2; t++) {
            int i = t * NTHR + tid;
            if (i < M_DIM) s_lam[i] = __ldcg(&g_lam[i]);
        }
        __syncthreads();

        int g  = tid >> 6;
        int jc = tid & 63;
        if (jc < nc) {
            float acc = 0.f;
            for (int i = g; i < M_DIM; i += 16)
                acc += A[(size_t)i * N_DIM + c0 + jc] * s_lam[i];
            s_red[g * 64 + jc] = acc;
        }
        __syncthreads();
        if (tid < nc) {
            float dot = 0.f;
            #pragma unroll
            for (int gg = 0; gg < 16; gg++) dot += s_red[gg * 64 + tid];
            out[N_DIM + M_DIM + c0 + tid] = fmaxf(0.f, c_sm[tid] - dot);
        }
    }
}

// ---------------------------------------------------------------------------
// kernel_launch: 2 graph nodes (init, pdhg). Inputs (metadata order):
//   d_in[0] = c (8192), d_in[1] = A (2048*8192), d_in[2] = b (2048)
// Output: 18432 floats = concat(x[8192], lam[2048], nu[8192])
// ---------------------------------------------------------------------------
extern "C" void kernel_launch(void* const* d_in, const int* in_sizes, int n_in,
                              void* d_out, int out_size) {
    const float* c = (const float*)d_in[0];
    const float* A = (const float*)d_in[1];
    const float* b = (const float*)d_in[2];
    float* out = (float*)d_out;

    cudaFuncSetAttribute(pdhg_kernel,
                         cudaFuncAttributeMaxDynamicSharedMemorySize, SMEM_BYTES);

    init_kernel<<<32, 256>>>();
    pdhg_kernel<<<NBLK, NTHR, SMEM_BYTES>>>(A, b, c, out);
}

// round 16
// speedup vs baseline: 1.0611x; 1.0611x over previous
#include <cuda_runtime.h>
#include <cuda_fp16.h>

#define M_DIM 2048
#define N_DIM 8192
#define N_ITERS 1000
#define TAU 1e-4f
#define SIGMA 1e-4f
#define NBLK 148
#define NTHR 1024

#define PROWS 13            // panel rows resident in SMEM (+1 register row)
#define PPAD 160            // padded partial rows: 148 real + 12 static-zero

// ---------------- device globals (allocation-free scratch) ----------------
__device__ float g_xbar[N_DIM];
__device__ float g_lam[M_DIM];
__device__ float g_part[PPAD * N_DIM];    // rows 148+ never written -> stay 0
__device__ unsigned g_flags[NBLK * 32];   // 1 flag / 128B line

// ---------------- smem layout (bytes) ----------------
#define OFF_PANEL 0                        // 13 rows x 8192 half = 212992
#define OFF_RED   (PROWS * N_DIM * 2)      // 16x64 fp32 = 4096
#define OFF_Y     (OFF_RED + 4096)         // 16 fp32
#define OFF_X     (OFF_Y + 64)             // 64 fp32
#define OFF_C     (OFF_X + 256)            // 64 fp32
#define OFF_B     (OFF_C + 256)            // 16 fp32
#define SMEM_BYTES (OFF_B + 64)
#define OFF_LAM   0                        // finale reuse of panel: 2048 fp32

// ---------------------------------------------------------------------------
__global__ void init_kernel() {
    int i = blockIdx.x * blockDim.x + threadIdx.x;
    if (i < N_DIM) g_xbar[i] = 0.f;
    if (i < NBLK * 32) g_flags[i] = 0u;
}

// ---- GPU-scope sync primitives (R13-proven) --------------------------------
__device__ __forceinline__ unsigned ld_relaxed(const unsigned* p) {
    unsigned v;
    asm volatile("ld.relaxed.gpu.global.u32 %0, [%1];" : "=r"(v) : "l"(p) : "memory");
    return v;
}
__device__ __forceinline__ void st_release(unsigned* p, unsigned v) {
    asm volatile("st.release.gpu.global.u32 [%0], %1;" :: "l"(p), "r"(v) : "memory");
}
__device__ __forceinline__ void fence_acq() {
    asm volatile("fence.acq_rel.gpu;" ::: "memory");
}
__device__ __forceinline__ void grid_barrier(unsigned target) {
    __syncthreads();
    if (threadIdx.x == 0)
        st_release(&g_flags[blockIdx.x * 32], target);
    if (threadIdx.x < NBLK) {
        while (ld_relaxed(&g_flags[threadIdx.x * 32]) < target) { }
        fence_acq();
    }
    __syncthreads();
}

// convert 8 fp16 (uint4) -> 8 fp32
__device__ __forceinline__ void cvt8(uint4 a, float* f) {
    float2 t;
    t = __half22float2(*reinterpret_cast<__half2*>(&a.x)); f[0] = t.x; f[1] = t.y;
    t = __half22float2(*reinterpret_cast<__half2*>(&a.y)); f[2] = t.x; f[3] = t.y;
    t = __half22float2(*reinterpret_cast<__half2*>(&a.z)); f[4] = t.x; f[5] = t.y;
    t = __half22float2(*reinterpret_cast<__half2*>(&a.w)); f[6] = t.x; f[7] = t.y;
}

// pack 8 fp32 -> uint4 of fp16
__device__ __forceinline__ uint4 pack8(float4 v0, float4 v1) {
    uint4 h;
    *reinterpret_cast<__half2*>(&h.x) = __floats2half2_rn(v0.x, v0.y);
    *reinterpret_cast<__half2*>(&h.y) = __floats2half2_rn(v0.z, v0.w);
    *reinterpret_cast<__half2*>(&h.z) = __floats2half2_rn(v1.x, v1.y);
    *reinterpret_cast<__half2*>(&h.w) = __floats2half2_rn(v1.z, v1.w);
    return h;
}

// ---------------------------------------------------------------------------
__global__ void __launch_bounds__(NTHR, 1)
pdhg_kernel(const float* __restrict__ A, const float* __restrict__ b,
            const float* __restrict__ c, float* __restrict__ out) {
    extern __shared__ char sm[];
    const int tid  = threadIdx.x;
    const int warp = tid >> 5;
    const int lane = tid & 31;
    const int blk  = blockIdx.x;

    const int r0 = (blk * M_DIM) / NBLK;
    const int nr = ((blk + 1) * M_DIM) / NBLK - r0;   // 13 or 14
    const int c0 = (blk * N_DIM) / NBLK;
    const int nc = ((blk + 1) * N_DIM) / NBLK - c0;   // 55 or 56

    float* s_red = (float*)(sm + OFF_RED);
    float* y_sm  = (float*)(sm + OFF_Y);
    float* x_sm  = (float*)(sm + OFF_X);
    float* c_sm  = (float*)(sm + OFF_C);
    float* b_sm  = (float*)(sm + OFF_B);
    const uint4* P4 = (const uint4*)(sm + OFF_PANEL);

    // ---- prologue: convert this block's 13 fp32 rows -> fp16 SMEM panel;
    //      14th row -> fp16 registers forever.
    {
        const float4* A4 = (const float4*)A;
        uint4* W4 = (uint4*)(sm + OFF_PANEL);
        for (int r = 0; r < PROWS; r++) {
            float4 v0 = A4[((size_t)(r0 + r)) * 2048 + 2 * tid];
            float4 v1 = A4[((size_t)(r0 + r)) * 2048 + 2 * tid + 1];
            W4[r * 1024 + tid] = pack8(v0, v1);
        }
        if (tid < 16) y_sm[tid] = 0.f;
        if (tid < nr) b_sm[tid] = b[r0 + tid];
        if (tid < nc) { x_sm[tid] = 0.f; c_sm[tid] = c[c0 + tid]; }
    }
    uint4 a_stream;
    {
        const float4* A4 = (const float4*)A;
        float4 v0 = A4[((size_t)(r0 + PROWS)) * 2048 + 2 * tid];
        float4 v1 = A4[((size_t)(r0 + PROWS)) * 2048 + 2 * tid + 1];
        a_stream = pack8(v0, v1);
    }
    __syncthreads();

    unsigned epoch = 0;
    uint4 a_pre = P4[tid];                 // row-0 hoist (panel is immutable)

    for (int it = 0; it < N_ITERS; it++) {
        // ================= Phase Y: y = min(0, y + s*(A@xbar) - s*b) =======
        float v[16];
        {
            const float4* gx4 = (const float4*)g_xbar;
            float4 xa = __ldcg(gx4 + 2 * tid);        // L2-coherent read
            float4 xb = __ldcg(gx4 + 2 * tid + 1);

            #pragma unroll
            for (int i = 0; i < 14; i++) {
                uint4 a = (i == 0) ? a_pre
                        : (i < PROWS) ? P4[i * 1024 + tid] : a_stream;
                float f[8];
                cvt8(a, f);
                v[i] = f[0] * xa.x + f[1] * xa.y + f[2] * xa.z + f[3] * xa.w +
                       f[4] * xb.x + f[5] * xb.y + f[6] * xb.z + f[7] * xb.w;
            }
            v[14] = 0.f; v[15] = 0.f;
        }
        // butterfly multi-row warp reduction (R8-proven)
        {
            #pragma unroll
            for (int k = 0; k < 8; k++) {
                float s = (lane & 16) ? v[k] : v[k + 8];
                float r = __shfl_xor_sync(0xffffffffu, s, 16);
                v[k] = ((lane & 16) ? v[k + 8] : v[k]) + r;
            }
            #pragma unroll
            for (int k = 0; k < 4; k++) {
                float s = (lane & 8) ? v[k] : v[k + 4];
                float r = __shfl_xor_sync(0xffffffffu, s, 8);
                v[k] = ((lane & 8) ? v[k + 4] : v[k]) + r;
            }
            #pragma unroll
            for (int k = 0; k < 2; k++) {
                float s = (lane & 4) ? v[k] : v[k + 2];
                float r = __shfl_xor_sync(0xffffffffu, s, 4);
                v[k] = ((lane & 4) ? v[k + 2] : v[k]) + r;
            }
            {
                float s = (lane & 2) ? v[0] : v[1];
                float r = __shfl_xor_sync(0xffffffffu, s, 2);
                v[0] = ((lane & 2) ? v[1] : v[0]) + r;
            }
            v[0] += __shfl_xor_sync(0xffffffffu, v[0], 1);
            int row = (((lane >> 4) & 1) << 3) | (((lane >> 3) & 1) << 2) |
                      (((lane >> 2) & 1) << 1) | ((lane >> 1) & 1);
            if ((lane & 1) == 0) s_red[row * 32 + warp] = v[0];
        }
        __syncthreads();
        if (warp < 16) {
            float t = s_red[warp * 32 + lane];
            #pragma unroll
            for (int o = 16; o > 0; o >>= 1)
                t += __shfl_down_sync(0xffffffffu, t, o);
            if (lane == 0 && warp < nr)
                y_sm[warp] = fminf(0.f, y_sm[warp] + SIGMA * t - SIGMA * b_sm[warp]);
        }
        __syncthreads();

        // ============ Phase X partials: part[j] = sum_i A[i][j]*y[i] =======
        {
            float o0 = 0.f, o1 = 0.f, o2 = 0.f, o3 = 0.f;
            float o4 = 0.f, o5 = 0.f, o6 = 0.f, o7 = 0.f;
            #pragma unroll
            for (int i = 0; i < 14; i++) {
                float yv = y_sm[i];                    // 0 for padded row
                uint4 a = (i == 0) ? a_pre
                        : (i < PROWS) ? P4[i * 1024 + tid] : a_stream;
                float f[8];
                cvt8(a, f);
                o0 += f[0] * yv; o1 += f[1] * yv; o2 += f[2] * yv; o3 += f[3] * yv;
                o4 += f[4] * yv; o5 += f[5] * yv; o6 += f[6] * yv; o7 += f[7] * yv;
            }
            float4* O4 = (float4*)(g_part + (size_t)blk * N_DIM + tid * 8);
            __stcg(O4,     make_float4(o0, o1, o2, o3));   // L2-only store
            __stcg(O4 + 1, make_float4(o4, o5, o6, o7));
        }
        grid_barrier(++epoch);

        // ===== Reduce partials: branch-free 10 loads (rows 148+ static 0) ==
        {
            int g  = tid >> 6;
            int jc = tid & 63;
            if (jc < nc) {
                float r = 0.f;
                #pragma unroll
                for (int k = 0; k < 10; k++)
                    r += __ldcg(g_part + (size_t)(g + k * 16) * N_DIM + c0 + jc);
                s_red[g * 64 + jc] = r;
            }
            __syncthreads();
            if (tid < nc) {
                float dot = 0.f;
                #pragma unroll
                for (int gg = 0; gg < 16; gg++) dot += s_red[gg * 64 + tid];
                float xo = x_sm[tid];
                float xn = fmaxf(0.f, xo - TAU * dot - TAU * c_sm[tid]);
                x_sm[tid] = xn;
                __stcg(&g_xbar[c0 + tid], 2.f * xn - xo);
            }
        }
        a_pre = P4[tid];                   // re-hoist row 0 before the barrier
        grid_barrier(++epoch);
    }

    // ---- Finalize: out = [x, lam, nu] ----
    if (tid < nc) out[c0 + tid] = x_sm[tid];
    if (tid < nr) {
        float l = fmaxf(0.f, -y_sm[tid]);
        __stcg(&g_lam[r0 + tid], l);
        out[N_DIM + r0 + tid] = l;
    }
    grid_barrier(++epoch);

    // nu = relu(c - A^T @ lam), against ORIGINAL fp32 A (one pass, accuracy)
    {
        float* s_lam = (float*)(sm + OFF_LAM);
        #pragma unroll
        for (int t = 0; t < 2; t++) {
            int i = t * NTHR + tid;
            if (i < M_DIM) s_lam[i] = __ldcg(&g_lam[i]);
        }
        __syncthreads();

        int g  = tid >> 6;
        int jc = tid & 63;
        if (jc < nc) {
            float acc = 0.f;
            for (int i = g; i < M_DIM; i += 16)
                acc += A[(size_t)i * N_DIM + c0 + jc] * s_lam[i];
            s_red[g * 64 + jc] = acc;
        }
        __syncthreads();
        if (tid < nc) {
            float dot = 0.f;
            #pragma unroll
            for (int gg = 0; gg < 16; gg++) dot += s_red[gg * 64 + tid];
            out[N_DIM + M_DIM + c0 + tid] = fmaxf(0.f, c_sm[tid] - dot);
        }
    }
}

// ---------------------------------------------------------------------------
// kernel_launch: 2 graph nodes (init, pdhg). Inputs (metadata order):
//   d_in[0] = c (8192), d_in[1] = A (2048*8192), d_in[2] = b (2048)
// Output: 18432 floats = concat(x[8192], lam[2048], nu[8192])
// ---------------------------------------------------------------------------
extern "C" void kernel_launch(void* const* d_in, const int* in_sizes, int n_in,
                              void* d_out, int out_size) {
    const float* c = (const float*)d_in[0];
    const float* A = (const float*)d_in[1];
    const float* b = (const float*)d_in[2];
    float* out = (float*)d_out;

    cudaFuncSetAttribute(pdhg_kernel,
                         cudaFuncAttributeMaxDynamicSharedMemorySize, SMEM_BYTES);

    init_kernel<<<32, 256>>>();
    pdhg_kernel<<<NBLK, NTHR, SMEM_BYTES>>>(A, b, c, out);
}